// round 1
// baseline (speedup 1.0000x reference)
#include <cuda_runtime.h>
#include <cstdint>
#include <cstddef>

#define B_  64
#define T_  1024
#define F_  512
#define H_  512
#define G4_ 2048   // 4H
#define NCTA 128

// Scratch (static device allocs are the sanctioned mechanism)
__device__ float g_xproj[(size_t)T_ * B_ * G4_];   // [t][b][col]  512 MB
__device__ float g_hbuf[2][H_ * B_];               // [col][b] transposed, double-buffered
__device__ unsigned g_flags[NCTA];                 // grid-barrier flags (monotonic across replays)

// ---------------------------------------------------------------------------
// Kernel 1: x_proj = inputs @ Wx + bias
//   A: [M=B*T, K=512] (row m = b*T+t, naturally contiguous in `inputs`)
//   W: [512, 2048] row-major
//   C stored as g_xproj[(t*64 + b)*2048 + n]
// Tiled fp32: BM=64, BN=64, BK=16, 256 threads, 4x4 per thread.
// ---------------------------------------------------------------------------
__global__ void __launch_bounds__(256) gemm_xproj(
    const float* __restrict__ A,
    const float* __restrict__ W,
    const float* __restrict__ bias)
{
    __shared__ float As[16 * 64];   // [k][m]
    __shared__ float Bs[16 * 64];   // [k][n]

    const int tid = threadIdx.x;
    const int bx  = blockIdx.x;     // n tile (0..31)
    const int by  = blockIdx.y;     // m tile (0..1023)
    const int tx  = tid & 15;       // n/4
    const int ty  = tid >> 4;       // m/4
    const int m0  = by * 64;
    const int n0  = bx * 64;

    const int ar = tid >> 2, ac = tid & 3;   // A load: row ar, float4 col ac
    const int br = tid >> 4, bc = tid & 15;  // B load: row br, float4 col bc

    const float* Aptr = A + (size_t)(m0 + ar) * 512 + ac * 4;
    const float* Bptr = W + (size_t)br * G4_ + n0 + bc * 4;

    float acc[4][4] = {};

    for (int k0 = 0; k0 < 512; k0 += 16) {
        float4 av = *(const float4*)(Aptr + k0);
        float4 bv = *(const float4*)(Bptr + (size_t)k0 * G4_);
        __syncthreads();
        // transpose-store A tile: As[k][m]
        As[(ac * 4 + 0) * 64 + ar] = av.x;
        As[(ac * 4 + 1) * 64 + ar] = av.y;
        As[(ac * 4 + 2) * 64 + ar] = av.z;
        As[(ac * 4 + 3) * 64 + ar] = av.w;
        *(float4*)&Bs[br * 64 + bc * 4] = bv;
        __syncthreads();

#pragma unroll
        for (int kk = 0; kk < 16; kk++) {
            float4 a  = *(const float4*)&As[kk * 64 + ty * 4];
            float4 b4 = *(const float4*)&Bs[kk * 64 + tx * 4];
            acc[0][0] = fmaf(a.x, b4.x, acc[0][0]);
            acc[0][1] = fmaf(a.x, b4.y, acc[0][1]);
            acc[0][2] = fmaf(a.x, b4.z, acc[0][2]);
            acc[0][3] = fmaf(a.x, b4.w, acc[0][3]);
            acc[1][0] = fmaf(a.y, b4.x, acc[1][0]);
            acc[1][1] = fmaf(a.y, b4.y, acc[1][1]);
            acc[1][2] = fmaf(a.y, b4.z, acc[1][2]);
            acc[1][3] = fmaf(a.y, b4.w, acc[1][3]);
            acc[2][0] = fmaf(a.z, b4.x, acc[2][0]);
            acc[2][1] = fmaf(a.z, b4.y, acc[2][1]);
            acc[2][2] = fmaf(a.z, b4.z, acc[2][2]);
            acc[2][3] = fmaf(a.z, b4.w, acc[2][3]);
            acc[3][0] = fmaf(a.w, b4.x, acc[3][0]);
            acc[3][1] = fmaf(a.w, b4.y, acc[3][1]);
            acc[3][2] = fmaf(a.w, b4.z, acc[3][2]);
            acc[3][3] = fmaf(a.w, b4.w, acc[3][3]);
        }
    }

    const float4 bb = *(const float4*)(bias + n0 + tx * 4);
#pragma unroll
    for (int i = 0; i < 4; i++) {
        int m = m0 + ty * 4 + i;
        int t = m & (T_ - 1);
        int b = m >> 10;
        float4 o;
        o.x = acc[i][0] + bb.x;
        o.y = acc[i][1] + bb.y;
        o.z = acc[i][2] + bb.z;
        o.w = acc[i][3] + bb.w;
        *(float4*)&g_xproj[((size_t)(t * 64 + b) << 11) + n0 + tx * 4] = o;
    }
}

// ---------------------------------------------------------------------------
// Kernel 2: persistent LSTM recurrence.
// 128 CTAs x 256 threads (1 CTA/SM, all co-resident -> software grid barrier OK).
// CTA `cta` owns h-columns j in [cta*4, cta*4+4) and gate columns
//   {g*512 + cta*4 + j : g in 0..3, j in 0..3}  (16 columns).
// Wh tile [512][16] persists in smem for all 1024 steps.
// h (global, transposed [col][b], double-buffered) copied to smem per step via
// cp.async in 8 chunks of 64 k, double-buffered to overlap with FMA.
// Elementwise cell update is CTA-local; c stays in registers.
// One grid barrier per step (per-CTA flag array, monotonic targets).
// ---------------------------------------------------------------------------
__device__ __forceinline__ void cp16(float* dst, const float* src)
{
    unsigned d = (unsigned)__cvta_generic_to_shared(dst);
    asm volatile("cp.async.cg.shared.global [%0], [%1], 16;" :: "r"(d), "l"(src) : "memory");
}

__global__ void __launch_bounds__(256, 1) lstm_kernel(
    const float* __restrict__ Wh,
    float* __restrict__ out)
{
    extern __shared__ float smem[];
    float* sWh = smem;                  // [512][16]  = 8192 floats
    float* sh  = smem + 512 * 16;       // [2][64*64] = 8192 floats
    float* sg  = sh + 2 * 64 * 64;      // [64][17]   = 1088 floats

    const int tid = threadIdx.x;
    const int cta = blockIdx.x;

    const unsigned base = *(volatile unsigned*)&g_flags[cta];

    // Load persistent Wh tile: sWh[k][gi], col(gi) = (gi/4)*512 + cta*4 + (gi%4)
    for (int i = tid; i < 512 * 16; i += 256) {
        int k  = i >> 4;
        int gi = i & 15;
        int col = ((gi >> 2) << 9) + (cta << 2) + (gi & 3);
        sWh[i] = Wh[(size_t)k * G4_ + col];
    }
    // Zero h buffer 0 (32768 elems over 128 CTAs x 256 threads)
    g_hbuf[0][(cta << 8) + tid] = 0.f;

    __threadfence();
    __syncthreads();
    {   // barrier 0: init complete
        unsigned tgt = base + 1;
        if (tid == 0) *(volatile unsigned*)&g_flags[cta] = tgt;
        if (tid < NCTA)
            while ((int)(*(volatile unsigned*)&g_flags[tid] - tgt) < 0) __nanosleep(64);
        __threadfence();
        __syncthreads();
    }

    // matmul mapping: 4 outputs per thread (same b, 4 gate types is WRONG layout;
    // here: b = tid%64, gate-type group g4 = tid/64, j-cols via float4 of sWh)
    const int b    = tid & 63;
    const int g4   = tid >> 6;
    // elementwise mapping: one (b, j) pair per thread
    const int eb   = tid >> 2;
    const int ej   = tid & 3;
    const int colj = (cta << 2) + ej;
    float c_reg = 0.f;

    for (int t = 0; t < T_; t++) {
        const float* hsrc = g_hbuf[t & 1];

        // acc init from x_proj (one coalesced float4 per thread)
        const float4 xp = *(const float4*)(g_xproj
            + ((size_t)(t * 64 + b) << 11) + (g4 << 9) + (cta << 2));
        float a0 = xp.x, a1 = xp.y, a2 = xp.z, a3 = xp.w;

        // prologue: async-load chunk 0
        {
#pragma unroll
            for (int i = 0; i < 4; i++) {
                int v = (tid + i * 256) << 2;
                cp16(sh + v, hsrc + v);
            }
            asm volatile("cp.async.commit_group;" ::: "memory");
        }

        for (int ch = 0; ch < 8; ch++) {
            if (ch < 7) {
                const float* src = hsrc + ((ch + 1) << 12);
                float* dst = sh + (((ch + 1) & 1) << 12);
#pragma unroll
                for (int i = 0; i < 4; i++) {
                    int v = (tid + i * 256) << 2;
                    cp16(dst + v, src + v);
                }
                asm volatile("cp.async.commit_group;" ::: "memory");
                asm volatile("cp.async.wait_group 1;" ::: "memory");
            } else {
                asm volatile("cp.async.wait_group 0;" ::: "memory");
            }
            __syncthreads();

            const float* shb = sh + ((ch & 1) << 12);
            const float* wp  = sWh + (ch << 10) + (g4 << 2);
#pragma unroll 16
            for (int kk = 0; kk < 64; kk++) {
                float  hv = shb[(kk << 6) + b];
                float4 w  = *(const float4*)(wp + (kk << 4));
                a0 = fmaf(hv, w.x, a0);
                a1 = fmaf(hv, w.y, a1);
                a2 = fmaf(hv, w.z, a2);
                a3 = fmaf(hv, w.w, a3);
            }
            __syncthreads();
        }

        // gates -> smem (padded stride 17)
        sg[b * 17 + (g4 << 2) + 0] = a0;
        sg[b * 17 + (g4 << 2) + 1] = a1;
        sg[b * 17 + (g4 << 2) + 2] = a2;
        sg[b * 17 + (g4 << 2) + 3] = a3;
        __syncthreads();

        // elementwise cell update (CTA-local; gate order i,f,g,o)
        float vi = sg[eb * 17 + 0  + ej];
        float vf = sg[eb * 17 + 4  + ej];
        float vg = sg[eb * 17 + 8  + ej];
        float vo = sg[eb * 17 + 12 + ej];
        float si = 1.f / (1.f + __expf(-vi));
        float sf = 1.f / (1.f + __expf(-vf));
        float tg = tanhf(vg);
        float so = 1.f / (1.f + __expf(-vo));
        c_reg = sf * c_reg + si * tg;
        float hn = so * tanhf(c_reg);

        g_hbuf[(t + 1) & 1][(colj << 6) + eb] = hn;

        if (t == T_ - 1) {
            out[eb * H_ + colj]            = c_reg;   // c_fin
            out[B_ * H_ + eb * H_ + colj]  = hn;      // h_fin
        }

        __threadfence();
        __syncthreads();
        {   // grid barrier for step t
            unsigned tgt = base + 2 + (unsigned)t;
            if (tid == 0) *(volatile unsigned*)&g_flags[cta] = tgt;
            if (tid < NCTA)
                while ((int)(*(volatile unsigned*)&g_flags[tid] - tgt) < 0) __nanosleep(64);
            __threadfence();
            __syncthreads();
        }
    }
}

// ---------------------------------------------------------------------------
extern "C" void kernel_launch(void* const* d_in, const int* in_sizes, int n_in,
                              void* d_out, int out_size)
{
    const float* inputs = (const float*)d_in[0];  // [B, T, F]
    const float* Wx     = (const float*)d_in[1];  // [F, 4H]
    const float* Wh     = (const float*)d_in[2];  // [H, 4H]
    const float* bias   = (const float*)d_in[3];  // [4H]
    float* out = (float*)d_out;                   // [2, B, H] = (c_fin, h_fin)

    (void)in_sizes; (void)n_in; (void)out_size;

    // x_proj GEMM
    gemm_xproj<<<dim3(G4_ / 64, (B_ * T_) / 64), 256>>>(inputs, Wx, bias);

    // persistent recurrence
    const int smem_bytes = (512 * 16 + 2 * 64 * 64 + 64 * 17) * (int)sizeof(float); // ~69.9 KB
    cudaFuncSetAttribute(lstm_kernel, cudaFuncAttributeMaxDynamicSharedMemorySize, smem_bytes);
    lstm_kernel<<<NCTA, 256, smem_bytes>>>(Wh, out);
}

// round 2
// speedup vs baseline: 1.2169x; 1.2169x over previous
#include <cuda_runtime.h>
#include <cstdint>
#include <cstddef>

#define B_  64
#define T_  1024
#define F_  512
#define H_  512
#define G4_ 2048   // 4H
#define NCTA 128

// Scratch (static device arrays are the sanctioned mechanism)
__device__ float g_xproj[(size_t)T_ * B_ * G4_];   // [t][b][col]
__device__ float g_hbuf[2][H_ * B_];               // [col(k)][b] transposed, double-buffered
__device__ unsigned g_flags[NCTA];                 // grid-barrier flags (monotonic across replays)

// ---------------------------------------------------------------------------
// helpers
// ---------------------------------------------------------------------------
__device__ __forceinline__ void cp16(float* dst, const float* src)
{
    unsigned d = (unsigned)__cvta_generic_to_shared(dst);
    asm volatile("cp.async.cg.shared.global [%0], [%1], 16;" :: "r"(d), "l"(src) : "memory");
}

// lo part of the 3xTF32 split: x - truncate_to_tf32(x)  (exact in fp32)
__device__ __forceinline__ float tf32_lo(float x)
{
    unsigned u = __float_as_uint(x) & 0xFFFFE000u;
    return x - __uint_as_float(u);
}

__device__ __forceinline__ void mma8(float* c,
    unsigned a0, unsigned a1, unsigned a2, unsigned a3,
    unsigned b0, unsigned b1)
{
    asm volatile(
        "mma.sync.aligned.m16n8k8.row.col.f32.tf32.tf32.f32 "
        "{%0,%1,%2,%3}, {%4,%5,%6,%7}, {%8,%9}, {%0,%1,%2,%3};"
        : "+f"(c[0]), "+f"(c[1]), "+f"(c[2]), "+f"(c[3])
        : "r"(a0), "r"(a1), "r"(a2), "r"(a3), "r"(b0), "r"(b1));
}

// ---------------------------------------------------------------------------
// Kernel 1: x_proj = inputs @ Wx + bias   (3xTF32 tensor-core GEMM)
//   A: [M=65536, K=512] (row m = b*1024 + t), W: [512, 2048]
//   C -> g_xproj[(t*64+b)*2048 + n]
// CTA tile 128x128x32, 8 warps (2m x 4n), warp tile 64x32.
// smem: As [128][36] (pad->conflict-free A frags), Bs [32][136], double-buffered.
// ---------------------------------------------------------------------------
#define AS_STRIDE 36
#define BS_STRIDE 136
#define AS_SZ (128 * AS_STRIDE)
#define BS_SZ (32 * BS_STRIDE)

__global__ void __launch_bounds__(256, 1) gemm_xproj(
    const float* __restrict__ A,
    const float* __restrict__ W,
    const float* __restrict__ bias)
{
    extern __shared__ float gs[];
    float* As = gs;                 // 2 * 128*36
    float* Bs = gs + 2 * AS_SZ;     // 2 * 32*136

    const int tid  = threadIdx.x;
    const int n0   = blockIdx.x * 128;
    const int m0   = blockIdx.y * 128;
    const int warp = tid >> 5, lane = tid & 31;
    const int wm   = warp & 1,  wn  = warp >> 1;
    const int r    = lane >> 2, cq  = lane & 3;

    float acc[4][4][4];
#pragma unroll
    for (int i = 0; i < 4; i++)
#pragma unroll
        for (int j = 0; j < 4; j++)
#pragma unroll
            for (int k = 0; k < 4; k++) acc[i][j][k] = 0.f;

    auto issue = [&](int s, int bi) {
        const float* Ag = A + (size_t)m0 * 512 + s * 32;
        float* Ad = As + bi * AS_SZ;
#pragma unroll
        for (int j = 0; j < 4; j++) {
            int q = tid + j * 256;
            int row = q >> 3, seg = q & 7;
            cp16(Ad + row * AS_STRIDE + seg * 4, Ag + (size_t)row * 512 + seg * 4);
        }
        const float* Bg = W + (size_t)(s * 32) * G4_ + n0;
        float* Bd = Bs + bi * BS_SZ;
#pragma unroll
        for (int j = 0; j < 4; j++) {
            int q = tid + j * 256;
            int row = q >> 5, seg = q & 31;
            cp16(Bd + row * BS_STRIDE + seg * 4, Bg + (size_t)row * G4_ + seg * 4);
        }
        asm volatile("cp.async.commit_group;" ::: "memory");
    };

    issue(0, 0);

    for (int s = 0; s < 16; s++) {
        if (s < 15) {
            issue(s + 1, (s + 1) & 1);
            asm volatile("cp.async.wait_group 1;" ::: "memory");
        } else {
            asm volatile("cp.async.wait_group 0;" ::: "memory");
        }
        __syncthreads();

        const float* Ab = As + (s & 1) * AS_SZ + (wm * 64) * AS_STRIDE;
        const float* Bb = Bs + (s & 1) * BS_SZ + wn * 32;

#pragma unroll
        for (int k8 = 0; k8 < 4; k8++) {
            unsigned aH[4][4], aL[4][4];
#pragma unroll
            for (int mt = 0; mt < 4; mt++) {
                const float* ap = Ab + (mt * 16 + r) * AS_STRIDE + k8 * 8 + cq;
                float x0 = ap[0];
                float x1 = ap[8 * AS_STRIDE];
                float x2 = ap[4];
                float x3 = ap[8 * AS_STRIDE + 4];
                aH[mt][0] = __float_as_uint(x0);
                aH[mt][1] = __float_as_uint(x1);
                aH[mt][2] = __float_as_uint(x2);
                aH[mt][3] = __float_as_uint(x3);
                aL[mt][0] = __float_as_uint(tf32_lo(x0));
                aL[mt][1] = __float_as_uint(tf32_lo(x1));
                aL[mt][2] = __float_as_uint(tf32_lo(x2));
                aL[mt][3] = __float_as_uint(tf32_lo(x3));
            }
            unsigned bH[4][2], bL[4][2];
#pragma unroll
            for (int nt = 0; nt < 4; nt++) {
                const float* bp = Bb + (k8 * 8 + cq) * BS_STRIDE + nt * 8 + r;
                float y0 = bp[0];
                float y1 = bp[4 * BS_STRIDE];
                bH[nt][0] = __float_as_uint(y0);
                bH[nt][1] = __float_as_uint(y1);
                bL[nt][0] = __float_as_uint(tf32_lo(y0));
                bL[nt][1] = __float_as_uint(tf32_lo(y1));
            }
#pragma unroll
            for (int mt = 0; mt < 4; mt++)
#pragma unroll
                for (int nt = 0; nt < 4; nt++) {
                    mma8(acc[mt][nt], aH[mt][0], aH[mt][1], aH[mt][2], aH[mt][3], bH[nt][0], bH[nt][1]);
                    mma8(acc[mt][nt], aL[mt][0], aL[mt][1], aL[mt][2], aL[mt][3], bH[nt][0], bH[nt][1]);
                    mma8(acc[mt][nt], aH[mt][0], aH[mt][1], aH[mt][2], aH[mt][3], bL[nt][0], bL[nt][1]);
                }
        }
        __syncthreads();
    }

    // epilogue: add bias, scatter to g_xproj [t*64+b][2048]
    const int mbase = m0 + wm * 64;
    const int nbase = n0 + wn * 32;
#pragma unroll
    for (int nt = 0; nt < 4; nt++) {
        int nn = nbase + nt * 8 + cq * 2;
        float2 bb = *(const float2*)(bias + nn);
#pragma unroll
        for (int mt = 0; mt < 4; mt++) {
            int row0 = mbase + mt * 16 + r;
            int t0 = row0 & (T_ - 1), bi0 = row0 >> 10;
            float2 v0 = make_float2(acc[mt][nt][0] + bb.x, acc[mt][nt][1] + bb.y);
            *(float2*)&g_xproj[((size_t)(t0 * 64 + bi0) << 11) + nn] = v0;
            int row1 = row0 + 8;
            int t1 = row1 & (T_ - 1), bi1 = row1 >> 10;
            float2 v1 = make_float2(acc[mt][nt][2] + bb.x, acc[mt][nt][3] + bb.y);
            *(float2*)&g_xproj[((size_t)(t1 * 64 + bi1) << 11) + nn] = v1;
        }
    }
}

// ---------------------------------------------------------------------------
// Kernel 2: persistent LSTM recurrence, 3xTF32 MMA inner product.
// 128 CTAs x 256 thr (1/SM). CTA owns 16 gate cols: n -> col (n>>2)*512 + cta*4 + (n&3).
// Wh slice decomposed hi/lo in smem once: sWhH/sWhL [512][24] (conflict-free B frags).
// h streamed per step in 8 chunks of 64 k -> sh [3][64][72] (conflict-free A frags),
// 3-stage cp.async ring. Warps: mtile = warp&3 (16 batch rows), khalf = warp>>2
// (even/odd ktiles of each chunk); split-k partials reduced through smem.
// ---------------------------------------------------------------------------
#define WH_STRIDE 24
#define SH_STRIDE 72
#define SH_CHUNK (64 * SH_STRIDE)
#define SG_STRIDE 18

__global__ void __launch_bounds__(256, 1) lstm_kernel(
    const float* __restrict__ Wh,
    float* __restrict__ out)
{
    extern __shared__ float smem[];
    float* sWhH = smem;                         // 512*24 = 12288
    float* sWhL = sWhH + 512 * WH_STRIDE;       // 12288
    float* sh   = sWhL + 512 * WH_STRIDE;       // 3 * 64*72 = 13824
    float* sg   = sh + 3 * SH_CHUNK;            // 2 * 64*18 = 2304

    const int tid = threadIdx.x;
    const int cta = blockIdx.x;

    const unsigned base = *(volatile unsigned*)&g_flags[cta];

    // decompose Wh slice into hi/lo (hi stored as raw fp32: HW truncates to tf32)
    for (int i = tid; i < 512 * 16; i += 256) {
        int k = i >> 4, n = i & 15;
        int col = ((n >> 2) << 9) + (cta << 2) + (n & 3);
        float w = Wh[(size_t)k * G4_ + col];
        sWhH[k * WH_STRIDE + n] = w;
        sWhL[k * WH_STRIDE + n] = tf32_lo(w);
    }
    g_hbuf[0][(cta << 8) + tid] = 0.f;

    __threadfence();
    __syncthreads();
    {   // barrier 0: init complete
        unsigned tgt = base + 1;
        if (tid == 0) *(volatile unsigned*)&g_flags[cta] = tgt;
        if (tid < NCTA)
            while ((int)(*(volatile unsigned*)&g_flags[tid] - tgt) < 0) __nanosleep(64);
        __threadfence();
        __syncthreads();
    }

    const int warp  = tid >> 5, lane = tid & 31;
    const int mtile = warp & 3, khalf = warp >> 2;
    const int r     = lane >> 2, cq = lane & 3;
    const int eb    = tid >> 2, ej = tid & 3;
    const int colj  = (cta << 2) + ej;
    float c_reg = 0.f;

    for (int t = 0; t < T_; t++) {
        const float* hsrc = g_hbuf[t & 1];
        float acc[2][4] = {{0.f, 0.f, 0.f, 0.f}, {0.f, 0.f, 0.f, 0.f}};

        // prologue: chunk 0 -> ring buf 0
        {
            const float* src = hsrc;
            float* dst = sh;
#pragma unroll
            for (int j = 0; j < 4; j++) {
                int i = tid + j * 256;
                int row = i >> 4, seg = i & 15;
                cp16(dst + row * SH_STRIDE + seg * 4, src + row * 64 + seg * 4);
            }
            asm volatile("cp.async.commit_group;" ::: "memory");
        }

        for (int ch = 0; ch < 8; ch++) {
            if (ch < 7) {
                const float* src = hsrc + ((ch + 1) << 12);
                float* dst = sh + ((ch + 1) % 3) * SH_CHUNK;
#pragma unroll
                for (int j = 0; j < 4; j++) {
                    int i = tid + j * 256;
                    int row = i >> 4, seg = i & 15;
                    cp16(dst + row * SH_STRIDE + seg * 4, src + row * 64 + seg * 4);
                }
                asm volatile("cp.async.commit_group;" ::: "memory");
                asm volatile("cp.async.wait_group 1;" ::: "memory");
            } else {
                asm volatile("cp.async.wait_group 0;" ::: "memory");
            }
            __syncthreads();

            const float* hb = sh + (ch % 3) * SH_CHUNK;
#pragma unroll
            for (int q = 0; q < 4; q++) {
                const int lk0 = ((q << 1) + khalf) << 3;   // local k base in [0,64)
                const float* ap = hb + (lk0 + cq) * SH_STRIDE + mtile * 16 + r;
                float x0 = ap[0];
                float x1 = ap[8];
                float x2 = ap[4 * SH_STRIDE];
                float x3 = ap[4 * SH_STRIDE + 8];
                unsigned aH0 = __float_as_uint(x0), aH1 = __float_as_uint(x1);
                unsigned aH2 = __float_as_uint(x2), aH3 = __float_as_uint(x3);
                unsigned aL0 = __float_as_uint(tf32_lo(x0));
                unsigned aL1 = __float_as_uint(tf32_lo(x1));
                unsigned aL2 = __float_as_uint(tf32_lo(x2));
                unsigned aL3 = __float_as_uint(tf32_lo(x3));

                const int kg = (ch << 6) + lk0;
#pragma unroll
                for (int nt = 0; nt < 2; nt++) {
                    const float* bpH = sWhH + (kg + cq) * WH_STRIDE + nt * 8 + r;
                    const float* bpL = sWhL + (kg + cq) * WH_STRIDE + nt * 8 + r;
                    unsigned bH0 = __float_as_uint(bpH[0]);
                    unsigned bH1 = __float_as_uint(bpH[4 * WH_STRIDE]);
                    unsigned bL0 = __float_as_uint(bpL[0]);
                    unsigned bL1 = __float_as_uint(bpL[4 * WH_STRIDE]);
                    mma8(acc[nt], aH0, aH1, aH2, aH3, bH0, bH1);
                    mma8(acc[nt], aL0, aL1, aL2, aL3, bH0, bH1);
                    mma8(acc[nt], aH0, aH1, aH2, aH3, bL0, bL1);
                }
            }
        }

        // split-k partials -> smem (khalf selects buffer)
        {
            float* sgp = sg + khalf * (64 * SG_STRIDE);
            int b0 = mtile * 16 + r;
#pragma unroll
            for (int nt = 0; nt < 2; nt++) {
                int n = nt * 8 + cq * 2;
                *(float2*)&sgp[b0 * SG_STRIDE + n] = make_float2(acc[nt][0], acc[nt][1]);
                *(float2*)&sgp[(b0 + 8) * SG_STRIDE + n] = make_float2(acc[nt][2], acc[nt][3]);
            }
        }
        __syncthreads();

        // elementwise cell update: thread -> (eb, ej); gates i,f,g,o at n = g*4+ej
        {
            const size_t xb = ((size_t)(t * 64 + eb) << 11) + (cta << 2) + ej;
            float v[4];
#pragma unroll
            for (int g = 0; g < 4; g++) {
                int n = (g << 2) + ej;
                v[g] = sg[eb * SG_STRIDE + n] + sg[64 * SG_STRIDE + eb * SG_STRIDE + n]
                     + g_xproj[xb + ((size_t)g << 9)];
            }
            float si = 1.f / (1.f + __expf(-v[0]));
            float sf = 1.f / (1.f + __expf(-v[1]));
            float tg = tanhf(v[2]);
            float so = 1.f / (1.f + __expf(-v[3]));
            c_reg = sf * c_reg + si * tg;
            float hn = so * tanhf(c_reg);

            g_hbuf[(t + 1) & 1][(colj << 6) + eb] = hn;

            if (t == T_ - 1) {
                out[eb * H_ + colj]           = c_reg;   // c_fin
                out[B_ * H_ + eb * H_ + colj] = hn;      // h_fin
            }
        }

        __threadfence();
        __syncthreads();
        {   // grid barrier for step t
            unsigned tgt = base + 2 + (unsigned)t;
            if (tid == 0) *(volatile unsigned*)&g_flags[cta] = tgt;
            if (tid < NCTA)
                while ((int)(*(volatile unsigned*)&g_flags[tid] - tgt) < 0) __nanosleep(64);
            __threadfence();
            __syncthreads();
        }
    }
}

// ---------------------------------------------------------------------------
extern "C" void kernel_launch(void* const* d_in, const int* in_sizes, int n_in,
                              void* d_out, int out_size)
{
    const float* inputs = (const float*)d_in[0];  // [B, T, F]
    const float* Wx     = (const float*)d_in[1];  // [F, 4H]
    const float* Wh     = (const float*)d_in[2];  // [H, 4H]
    const float* bias   = (const float*)d_in[3];  // [4H]
    float* out = (float*)d_out;                   // [2, B, H] = (c_fin, h_fin)

    (void)in_sizes; (void)n_in; (void)out_size;

    const int gemm_smem = (2 * AS_SZ + 2 * BS_SZ) * (int)sizeof(float);   // 71680 B
    cudaFuncSetAttribute(gemm_xproj, cudaFuncAttributeMaxDynamicSharedMemorySize, gemm_smem);
    gemm_xproj<<<dim3(G4_ / 128, (B_ * T_) / 128), 256, gemm_smem>>>(inputs, Wx, bias);

    const int lstm_smem = (2 * 512 * WH_STRIDE + 3 * SH_CHUNK + 2 * 64 * SG_STRIDE) * (int)sizeof(float); // 162816 B
    cudaFuncSetAttribute(lstm_kernel, cudaFuncAttributeMaxDynamicSharedMemorySize, lstm_smem);
    lstm_kernel<<<NCTA, 256, lstm_smem>>>(Wh, out);
}

// round 3
// speedup vs baseline: 1.3224x; 1.0867x over previous
#include <cuda_runtime.h>
#include <cstdint>
#include <cstddef>

#define B_  64
#define T_  1024
#define F_  512
#define H_  512
#define G4_ 2048   // 4H
#define NCTA 128

__device__ float g_xproj[(size_t)T_ * B_ * G4_];   // [t][b][col]
__device__ float g_hbuf[2][H_ * B_];               // [col(k)][b] transposed, double-buffered
__device__ unsigned g_flags[NCTA];                 // grid-barrier flags (monotonic across replays)

// ---------------------------------------------------------------------------
__device__ __forceinline__ void cp16(float* dst, const float* src)
{
    unsigned d = (unsigned)__cvta_generic_to_shared(dst);
    asm volatile("cp.async.cg.shared.global [%0], [%1], 16;" :: "r"(d), "l"(src) : "memory");
}

// lo part of the tf32 split: x - truncate_to_tf32(x)  (exact in fp32)
__device__ __forceinline__ float tf32_lo(float x)
{
    unsigned u = __float_as_uint(x) & 0xFFFFE000u;
    return x - __uint_as_float(u);
}

__device__ __forceinline__ void mma8(float* c,
    unsigned a0, unsigned a1, unsigned a2, unsigned a3,
    unsigned b0, unsigned b1)
{
    asm volatile(
        "mma.sync.aligned.m16n8k8.row.col.f32.tf32.tf32.f32 "
        "{%0,%1,%2,%3}, {%4,%5,%6,%7}, {%8,%9}, {%0,%1,%2,%3};"
        : "+f"(c[0]), "+f"(c[1]), "+f"(c[2]), "+f"(c[3])
        : "r"(a0), "r"(a1), "r"(a2), "r"(a3), "r"(b0), "r"(b1));
}

// ---------------------------------------------------------------------------
// Kernel 1: x_proj = inputs @ Wx + bias  (2-term tf32: aH*bH + aH*bL)
// CTA tile 128x128x32, 8 warps (2m x 4n).
// ---------------------------------------------------------------------------
#define AS_STRIDE 36
#define BS_STRIDE 136
#define AS_SZ (128 * AS_STRIDE)
#define BS_SZ (32 * BS_STRIDE)

__global__ void __launch_bounds__(256, 1) gemm_xproj(
    const float* __restrict__ A,
    const float* __restrict__ W,
    const float* __restrict__ bias)
{
    extern __shared__ float gs[];
    float* As = gs;                 // 2 * 128*36
    float* Bs = gs + 2 * AS_SZ;     // 2 * 32*136

    const int tid = threadIdx.x;
    const int n0  = blockIdx.x * 128;
    const int m0  = blockIdx.y * 128;
    const int warp = tid >> 5, lane = tid & 31;
    const int wm = warp & 1, wn = warp >> 1;
    const int r  = lane >> 2, cq = lane & 3;

    float acc[4][4][4];
#pragma unroll
    for (int i = 0; i < 4; i++)
#pragma unroll
        for (int j = 0; j < 4; j++)
#pragma unroll
            for (int k = 0; k < 4; k++) acc[i][j][k] = 0.f;

    auto issue = [&](int s, int bi) {
        const float* Ag = A + (size_t)m0 * 512 + s * 32;
        float* Ad = As + bi * AS_SZ;
#pragma unroll
        for (int j = 0; j < 4; j++) {
            int q = tid + j * 256;
            int row = q >> 3, seg = q & 7;
            cp16(Ad + row * AS_STRIDE + seg * 4, Ag + (size_t)row * 512 + seg * 4);
        }
        const float* Bg = W + (size_t)(s * 32) * G4_ + n0;
        float* Bd = Bs + bi * BS_SZ;
#pragma unroll
        for (int j = 0; j < 4; j++) {
            int q = tid + j * 256;
            int row = q >> 5, seg = q & 31;
            cp16(Bd + row * BS_STRIDE + seg * 4, Bg + (size_t)row * G4_ + seg * 4);
        }
        asm volatile("cp.async.commit_group;" ::: "memory");
    };

    issue(0, 0);

    for (int s = 0; s < 16; s++) {
        if (s < 15) {
            issue(s + 1, (s + 1) & 1);
            asm volatile("cp.async.wait_group 1;" ::: "memory");
        } else {
            asm volatile("cp.async.wait_group 0;" ::: "memory");
        }
        __syncthreads();

        const float* Ab = As + (s & 1) * AS_SZ + (wm * 64) * AS_STRIDE;
        const float* Bb = Bs + (s & 1) * BS_SZ + wn * 32;

#pragma unroll
        for (int k8 = 0; k8 < 4; k8++) {
            unsigned aH[4][4];
#pragma unroll
            for (int mt = 0; mt < 4; mt++) {
                const float* ap = Ab + (mt * 16 + r) * AS_STRIDE + k8 * 8 + cq;
                aH[mt][0] = __float_as_uint(ap[0]);
                aH[mt][1] = __float_as_uint(ap[8 * AS_STRIDE]);
                aH[mt][2] = __float_as_uint(ap[4]);
                aH[mt][3] = __float_as_uint(ap[8 * AS_STRIDE + 4]);
            }
            unsigned bH[4][2], bL[4][2];
#pragma unroll
            for (int nt = 0; nt < 4; nt++) {
                const float* bp = Bb + (k8 * 8 + cq) * BS_STRIDE + nt * 8 + r;
                float y0 = bp[0];
                float y1 = bp[4 * BS_STRIDE];
                bH[nt][0] = __float_as_uint(y0);
                bH[nt][1] = __float_as_uint(y1);
                bL[nt][0] = __float_as_uint(tf32_lo(y0));
                bL[nt][1] = __float_as_uint(tf32_lo(y1));
            }
#pragma unroll
            for (int nt = 0; nt < 4; nt++)
#pragma unroll
                for (int mt = 0; mt < 4; mt++)
                    mma8(acc[mt][nt], aH[mt][0], aH[mt][1], aH[mt][2], aH[mt][3], bH[nt][0], bH[nt][1]);
#pragma unroll
            for (int nt = 0; nt < 4; nt++)
#pragma unroll
                for (int mt = 0; mt < 4; mt++)
                    mma8(acc[mt][nt], aH[mt][0], aH[mt][1], aH[mt][2], aH[mt][3], bL[nt][0], bL[nt][1]);
        }
        __syncthreads();
    }

    const int mbase = m0 + wm * 64;
    const int nbase = n0 + wn * 32;
#pragma unroll
    for (int nt = 0; nt < 4; nt++) {
        int nn = nbase + nt * 8 + cq * 2;
        float2 bb = *(const float2*)(bias + nn);
#pragma unroll
        for (int mt = 0; mt < 4; mt++) {
            int row0 = mbase + mt * 16 + r;
            int t0 = row0 & (T_ - 1), bi0 = row0 >> 10;
            float2 v0 = make_float2(acc[mt][nt][0] + bb.x, acc[mt][nt][1] + bb.y);
            *(float2*)&g_xproj[((size_t)(t0 * 64 + bi0) << 11) + nn] = v0;
            int row1 = row0 + 8;
            int t1 = row1 & (T_ - 1), bi1 = row1 >> 10;
            float2 v1 = make_float2(acc[mt][nt][2] + bb.x, acc[mt][nt][3] + bb.y);
            *(float2*)&g_xproj[((size_t)(t1 * 64 + bi1) << 11) + nn] = v1;
        }
    }
}

// ---------------------------------------------------------------------------
// Kernel 2: persistent LSTM recurrence.
// 128 CTAs x 256 thr (1/SM). CTA owns 16 gate cols: n -> col (n>>2)*512+cta*4+(n&3).
// Wh fragments (hi+lo) live in REGISTERS for the whole t-loop:
//   warp w owns global ktiles {16c + 8j + w : c 0..3, j 0..1} (8 ktiles of k8),
//   covers all 4 mtiles x 2 ntiles itself -> 64 B-regs, zero per-step B-LDS.
// h streamed per step in 4 chunks of 128 k-rows, 3-buffer cp.async ring,
// 1 syncthreads per chunk. A (=h) truncated to tf32 (2-term split).
// x_proj slice prefetched to smem at step start. 8-way split-k reduced via smem.
// ---------------------------------------------------------------------------
#define SH_STRIDE 72
#define SH_CHUNK (128 * SH_STRIDE)
#define SG_STRIDE 18
#define SG_WARP  (64 * SG_STRIDE)

__global__ void __launch_bounds__(256, 1) lstm_kernel(
    const float* __restrict__ Wh,
    float* __restrict__ out)
{
    extern __shared__ float smem[];
    float* sh = smem;                    // 3 * 128*72 = 27648 floats
    float* sg = sh + 3 * SH_CHUNK;       // 8 * 64*18  =  9216 floats
    float* sx = sg + 8 * SG_WARP;        // 64*16      =  1024 floats

    const int tid = threadIdx.x;
    const int cta = blockIdx.x;
    const int warp = tid >> 5, lane = tid & 31;
    const int r = lane >> 2, cq = lane & 3;

    const unsigned base = *(volatile unsigned*)&g_flags[cta];

    // Preload Wh fragments (hi + lo) into registers: 8 ktiles x 2 nt x 2 regs.
    unsigned BH[16][2], BL[16][2];
#pragma unroll
    for (int c = 0; c < 4; c++)
#pragma unroll
        for (int j = 0; j < 2; j++) {
            int kt = c * 16 + j * 8 + warp;
            int k0 = kt << 3;
#pragma unroll
            for (int nt = 0; nt < 2; nt++) {
                int n = nt * 8 + r;
                int col = ((n >> 2) << 9) + (cta << 2) + (n & 3);
                float w0 = Wh[(size_t)(k0 + cq) * G4_ + col];
                float w1 = Wh[(size_t)(k0 + cq + 4) * G4_ + col];
                int bi = (c << 2) | (j << 1) | nt;
                BH[bi][0] = __float_as_uint(w0);
                BH[bi][1] = __float_as_uint(w1);
                BL[bi][0] = __float_as_uint(tf32_lo(w0));
                BL[bi][1] = __float_as_uint(tf32_lo(w1));
            }
        }

    g_hbuf[0][(cta << 8) + tid] = 0.f;

    __threadfence();
    __syncthreads();
    {   // barrier 0: init complete
        unsigned tgt = base + 1;
        if (tid == 0) *(volatile unsigned*)&g_flags[cta] = tgt;
        if (tid < NCTA)
            while ((int)(*(volatile unsigned*)&g_flags[tid] - tgt) < 0) __nanosleep(64);
        __threadfence();
        __syncthreads();
    }

    const int eb = tid >> 2, ej = tid & 3;    // cell-update mapping
    const int colj = (cta << 2) + ej;
    float c_reg = 0.f;

    for (int t = 0; t < T_; t++) {
        const float* hsrc = g_hbuf[t & 1];

        // group 0: chunk 0 + x_proj slice; group 1: chunk 1
        {
#pragma unroll
            for (int j = 0; j < 8; j++) {
                int i = tid + j * 256;
                int row = i >> 4, seg = i & 15;
                cp16(sh + row * SH_STRIDE + seg * 4, hsrc + row * 64 + seg * 4);
            }
            int b = tid >> 2, g = tid & 3;
            cp16(sx + b * 16 + g * 4,
                 g_xproj + ((size_t)(t * 64 + b) << 11) + ((size_t)g << 9) + (cta << 2));
            asm volatile("cp.async.commit_group;" ::: "memory");
#pragma unroll
            for (int j = 0; j < 8; j++) {
                int i = tid + j * 256;
                int row = i >> 4, seg = i & 15;
                cp16(sh + SH_CHUNK + row * SH_STRIDE + seg * 4,
                     hsrc + 8192 + row * 64 + seg * 4);
            }
            asm volatile("cp.async.commit_group;" ::: "memory");
        }

        float acc[4][2][4];
#pragma unroll
        for (int mt = 0; mt < 4; mt++)
#pragma unroll
            for (int nt = 0; nt < 2; nt++)
#pragma unroll
                for (int k = 0; k < 4; k++) acc[mt][nt][k] = 0.f;

        for (int ch = 0; ch < 4; ch++) {
            if (ch < 3) { asm volatile("cp.async.wait_group 1;" ::: "memory"); }
            else        { asm volatile("cp.async.wait_group 0;" ::: "memory"); }
            __syncthreads();

            if (ch < 2) {   // issue chunk ch+2 into ring buffer (ch+2)%3
                const float* src = hsrc + (ch + 2) * 8192;
                float* dst = sh + ((ch + 2) % 3) * SH_CHUNK;
#pragma unroll
                for (int j = 0; j < 8; j++) {
                    int i = tid + j * 256;
                    int row = i >> 4, seg = i & 15;
                    cp16(dst + row * SH_STRIDE + seg * 4, src + row * 64 + seg * 4);
                }
                asm volatile("cp.async.commit_group;" ::: "memory");
            }

            const float* hb = sh + (ch % 3) * SH_CHUNK;
#pragma unroll
            for (int j = 0; j < 2; j++) {
                const int lk0 = ((j << 3) + warp) << 3;   // local k-row in [0,128)
                unsigned a[4][4];
#pragma unroll
                for (int mt = 0; mt < 4; mt++) {
                    const float* ap = hb + (lk0 + cq) * SH_STRIDE + mt * 16 + r;
                    a[mt][0] = __float_as_uint(ap[0]);
                    a[mt][1] = __float_as_uint(ap[8]);
                    a[mt][2] = __float_as_uint(ap[4 * SH_STRIDE]);
                    a[mt][3] = __float_as_uint(ap[4 * SH_STRIDE + 8]);
                }
                const int bi0 = (ch << 2) | (j << 1);
#pragma unroll
                for (int nt = 0; nt < 2; nt++)
#pragma unroll
                    for (int mt = 0; mt < 4; mt++)
                        mma8(acc[mt][nt], a[mt][0], a[mt][1], a[mt][2], a[mt][3],
                             BH[bi0 | nt][0], BH[bi0 | nt][1]);
#pragma unroll
                for (int nt = 0; nt < 2; nt++)
#pragma unroll
                    for (int mt = 0; mt < 4; mt++)
                        mma8(acc[mt][nt], a[mt][0], a[mt][1], a[mt][2], a[mt][3],
                             BL[bi0 | nt][0], BL[bi0 | nt][1]);
            }
        }

        // split-k partials -> smem
        {
            float* sgp = sg + warp * SG_WARP;
#pragma unroll
            for (int mt = 0; mt < 4; mt++) {
                int b0 = mt * 16 + r;
#pragma unroll
                for (int nt = 0; nt < 2; nt++) {
                    int n = nt * 8 + cq * 2;
                    *(float2*)&sgp[b0 * SG_STRIDE + n] =
                        make_float2(acc[mt][nt][0], acc[mt][nt][1]);
                    *(float2*)&sgp[(b0 + 8) * SG_STRIDE + n] =
                        make_float2(acc[mt][nt][2], acc[mt][nt][3]);
                }
            }
        }
        __syncthreads();

        // cell update: thread -> (eb, ej); gates i,f,g,o at n = g*4 + ej
        {
            float v[4];
#pragma unroll
            for (int g = 0; g < 4; g++) {
                int n = (g << 2) + ej;
                float s = sx[eb * 16 + n];
#pragma unroll
                for (int w = 0; w < 8; w++) s += sg[w * SG_WARP + eb * SG_STRIDE + n];
                v[g] = s;
            }
            float si = 1.f / (1.f + __expf(-v[0]));
            float sf = 1.f / (1.f + __expf(-v[1]));
            float tg = tanhf(v[2]);
            float so = 1.f / (1.f + __expf(-v[3]));
            c_reg = sf * c_reg + si * tg;
            float hn = so * tanhf(c_reg);

            g_hbuf[(t + 1) & 1][(colj << 6) + eb] = hn;

            if (t == T_ - 1) {
                out[eb * H_ + colj]           = c_reg;   // c_fin
                out[B_ * H_ + eb * H_ + colj] = hn;      // h_fin
            }
        }

        __threadfence();
        __syncthreads();
        {   // grid barrier for step t
            unsigned tgt = base + 2 + (unsigned)t;
            if (tid == 0) *(volatile unsigned*)&g_flags[cta] = tgt;
            if (tid < NCTA)
                while ((int)(*(volatile unsigned*)&g_flags[tid] - tgt) < 0) __nanosleep(64);
            __threadfence();
            __syncthreads();
        }
    }
}

// ---------------------------------------------------------------------------
extern "C" void kernel_launch(void* const* d_in, const int* in_sizes, int n_in,
                              void* d_out, int out_size)
{
    const float* inputs = (const float*)d_in[0];  // [B, T, F]
    const float* Wx     = (const float*)d_in[1];  // [F, 4H]
    const float* Wh     = (const float*)d_in[2];  // [H, 4H]
    const float* bias   = (const float*)d_in[3];  // [4H]
    float* out = (float*)d_out;                   // [2, B, H] = (c_fin, h_fin)

    (void)in_sizes; (void)n_in; (void)out_size;

    const int gemm_smem = (2 * AS_SZ + 2 * BS_SZ) * (int)sizeof(float);
    cudaFuncSetAttribute(gemm_xproj, cudaFuncAttributeMaxDynamicSharedMemorySize, gemm_smem);
    gemm_xproj<<<dim3(G4_ / 128, (B_ * T_) / 128), 256, gemm_smem>>>(inputs, Wx, bias);

    const int lstm_smem = (3 * SH_CHUNK + 8 * SG_WARP + 64 * 16) * (int)sizeof(float); // 151552 B
    cudaFuncSetAttribute(lstm_kernel, cudaFuncAttributeMaxDynamicSharedMemorySize, lstm_smem);
    lstm_kernel<<<NCTA, 256, lstm_smem>>>(Wh, out);
}

// round 4
// speedup vs baseline: 1.8564x; 1.4038x over previous
#include <cuda_runtime.h>
#include <cstdint>
#include <cstddef>

#define B_  64
#define T_  1024
#define F_  512
#define H_  512
#define G4_ 2048   // 4H
#define NCTA 128

__device__ float g_xproj[(size_t)T_ * B_ * G4_];   // [t][b][col]
__device__ float g_hbuf[2][H_ * B_];               // [col(k)][b] transposed, double-buffered
__device__ unsigned g_flags[NCTA];                 // grid-barrier flags (monotonic across replays)

// ---------------------------------------------------------------------------
__device__ __forceinline__ void cp16(float* dst, const float* src)
{
    unsigned d = (unsigned)__cvta_generic_to_shared(dst);
    asm volatile("cp.async.cg.shared.global [%0], [%1], 16;" :: "r"(d), "l"(src) : "memory");
}

__device__ __forceinline__ unsigned ld_acq(const unsigned* p)
{
    unsigned v;
    asm volatile("ld.acquire.gpu.global.u32 %0, [%1];" : "=r"(v) : "l"(p) : "memory");
    return v;
}

__device__ __forceinline__ void st_rel(unsigned* p, unsigned v)
{
    asm volatile("st.release.gpu.global.u32 [%0], %1;" :: "l"(p), "r"(v) : "memory");
}

// lo part of the tf32 split: x - truncate_to_tf32(x)  (exact in fp32)
__device__ __forceinline__ float tf32_lo(float x)
{
    unsigned u = __float_as_uint(x) & 0xFFFFE000u;
    return x - __uint_as_float(u);
}

__device__ __forceinline__ void mma8(float* c,
    unsigned a0, unsigned a1, unsigned a2, unsigned a3,
    unsigned b0, unsigned b1)
{
    asm volatile(
        "mma.sync.aligned.m16n8k8.row.col.f32.tf32.tf32.f32 "
        "{%0,%1,%2,%3}, {%4,%5,%6,%7}, {%8,%9}, {%0,%1,%2,%3};"
        : "+f"(c[0]), "+f"(c[1]), "+f"(c[2]), "+f"(c[3])
        : "r"(a0), "r"(a1), "r"(a2), "r"(a3), "r"(b0), "r"(b1));
}

// ---------------------------------------------------------------------------
// Kernel 1: x_proj = inputs @ Wx + bias  (2-term tf32: aH*bH + aH*bL)
// CTA tile 128x128x32, 8 warps (2m x 4n).   [unchanged from R3]
// ---------------------------------------------------------------------------
#define AS_STRIDE 36
#define BS_STRIDE 136
#define AS_SZ (128 * AS_STRIDE)
#define BS_SZ (32 * BS_STRIDE)

__global__ void __launch_bounds__(256, 1) gemm_xproj(
    const float* __restrict__ A,
    const float* __restrict__ W,
    const float* __restrict__ bias)
{
    extern __shared__ float gs[];
    float* As = gs;                 // 2 * 128*36
    float* Bs = gs + 2 * AS_SZ;     // 2 * 32*136

    const int tid = threadIdx.x;
    const int n0  = blockIdx.x * 128;
    const int m0  = blockIdx.y * 128;
    const int warp = tid >> 5, lane = tid & 31;
    const int wm = warp & 1, wn = warp >> 1;
    const int r  = lane >> 2, cq = lane & 3;

    float acc[4][4][4];
#pragma unroll
    for (int i = 0; i < 4; i++)
#pragma unroll
        for (int j = 0; j < 4; j++)
#pragma unroll
            for (int k = 0; k < 4; k++) acc[i][j][k] = 0.f;

    auto issue = [&](int s, int bi) {
        const float* Ag = A + (size_t)m0 * 512 + s * 32;
        float* Ad = As + bi * AS_SZ;
#pragma unroll
        for (int j = 0; j < 4; j++) {
            int q = tid + j * 256;
            int row = q >> 3, seg = q & 7;
            cp16(Ad + row * AS_STRIDE + seg * 4, Ag + (size_t)row * 512 + seg * 4);
        }
        const float* Bg = W + (size_t)(s * 32) * G4_ + n0;
        float* Bd = Bs + bi * BS_SZ;
#pragma unroll
        for (int j = 0; j < 4; j++) {
            int q = tid + j * 256;
            int row = q >> 5, seg = q & 31;
            cp16(Bd + row * BS_STRIDE + seg * 4, Bg + (size_t)row * G4_ + seg * 4);
        }
        asm volatile("cp.async.commit_group;" ::: "memory");
    };

    issue(0, 0);

    for (int s = 0; s < 16; s++) {
        if (s < 15) {
            issue(s + 1, (s + 1) & 1);
            asm volatile("cp.async.wait_group 1;" ::: "memory");
        } else {
            asm volatile("cp.async.wait_group 0;" ::: "memory");
        }
        __syncthreads();

        const float* Ab = As + (s & 1) * AS_SZ + (wm * 64) * AS_STRIDE;
        const float* Bb = Bs + (s & 1) * BS_SZ + wn * 32;

#pragma unroll
        for (int k8 = 0; k8 < 4; k8++) {
            unsigned aH[4][4];
#pragma unroll
            for (int mt = 0; mt < 4; mt++) {
                const float* ap = Ab + (mt * 16 + r) * AS_STRIDE + k8 * 8 + cq;
                aH[mt][0] = __float_as_uint(ap[0]);
                aH[mt][1] = __float_as_uint(ap[8 * AS_STRIDE]);
                aH[mt][2] = __float_as_uint(ap[4]);
                aH[mt][3] = __float_as_uint(ap[8 * AS_STRIDE + 4]);
            }
            unsigned bH[4][2], bL[4][2];
#pragma unroll
            for (int nt = 0; nt < 4; nt++) {
                const float* bp = Bb + (k8 * 8 + cq) * BS_STRIDE + nt * 8 + r;
                float y0 = bp[0];
                float y1 = bp[4 * BS_STRIDE];
                bH[nt][0] = __float_as_uint(y0);
                bH[nt][1] = __float_as_uint(y1);
                bL[nt][0] = __float_as_uint(tf32_lo(y0));
                bL[nt][1] = __float_as_uint(tf32_lo(y1));
            }
#pragma unroll
            for (int nt = 0; nt < 4; nt++)
#pragma unroll
                for (int mt = 0; mt < 4; mt++)
                    mma8(acc[mt][nt], aH[mt][0], aH[mt][1], aH[mt][2], aH[mt][3], bH[nt][0], bH[nt][1]);
#pragma unroll
            for (int nt = 0; nt < 4; nt++)
#pragma unroll
                for (int mt = 0; mt < 4; mt++)
                    mma8(acc[mt][nt], aH[mt][0], aH[mt][1], aH[mt][2], aH[mt][3], bL[nt][0], bL[nt][1]);
        }
        __syncthreads();
    }

    const int mbase = m0 + wm * 64;
    const int nbase = n0 + wn * 32;
#pragma unroll
    for (int nt = 0; nt < 4; nt++) {
        int nn = nbase + nt * 8 + cq * 2;
        float2 bb = *(const float2*)(bias + nn);
#pragma unroll
        for (int mt = 0; mt < 4; mt++) {
            int row0 = mbase + mt * 16 + r;
            int t0 = row0 & (T_ - 1), bi0 = row0 >> 10;
            float2 v0 = make_float2(acc[mt][nt][0] + bb.x, acc[mt][nt][1] + bb.y);
            *(float2*)&g_xproj[((size_t)(t0 * 64 + bi0) << 11) + nn] = v0;
            int row1 = row0 + 8;
            int t1 = row1 & (T_ - 1), bi1 = row1 >> 10;
            float2 v1 = make_float2(acc[mt][nt][2] + bb.x, acc[mt][nt][3] + bb.y);
            *(float2*)&g_xproj[((size_t)(t1 * 64 + bi1) << 11) + nn] = v1;
        }
    }
}

// ---------------------------------------------------------------------------
// Kernel 2: persistent LSTM recurrence.  [R3 structure; NEW barrier: no
// nanosleep, no __threadfence/CCTL.IVALL — syncthreads + st.release flag +
// pure-spin ld.acquire poll + syncthreads]
// ---------------------------------------------------------------------------
#define SH_STRIDE 72
#define SH_CHUNK (128 * SH_STRIDE)
#define SG_STRIDE 18
#define SG_WARP  (64 * SG_STRIDE)

__global__ void __launch_bounds__(256, 1) lstm_kernel(
    const float* __restrict__ Wh,
    float* __restrict__ out)
{
    extern __shared__ float smem[];
    float* sh = smem;                    // 3 * 128*72 = 27648 floats
    float* sg = sh + 3 * SH_CHUNK;       // 8 * 64*18  =  9216 floats
    float* sx = sg + 8 * SG_WARP;        // 64*16      =  1024 floats

    const int tid = threadIdx.x;
    const int cta = blockIdx.x;
    const int warp = tid >> 5, lane = tid & 31;
    const int r = lane >> 2, cq = lane & 3;

    const unsigned base = ld_acq(&g_flags[cta]);

    // Preload Wh fragments (hi + lo) into registers: 8 ktiles x 2 nt x 2 regs.
    unsigned BH[16][2], BL[16][2];
#pragma unroll
    for (int c = 0; c < 4; c++)
#pragma unroll
        for (int j = 0; j < 2; j++) {
            int kt = c * 16 + j * 8 + warp;
            int k0 = kt << 3;
#pragma unroll
            for (int nt = 0; nt < 2; nt++) {
                int n = nt * 8 + r;
                int col = ((n >> 2) << 9) + (cta << 2) + (n & 3);
                float w0 = Wh[(size_t)(k0 + cq) * G4_ + col];
                float w1 = Wh[(size_t)(k0 + cq + 4) * G4_ + col];
                int bi = (c << 2) | (j << 1) | nt;
                BH[bi][0] = __float_as_uint(w0);
                BH[bi][1] = __float_as_uint(w1);
                BL[bi][0] = __float_as_uint(tf32_lo(w0));
                BL[bi][1] = __float_as_uint(tf32_lo(w1));
            }
        }

    g_hbuf[0][(cta << 8) + tid] = 0.f;

    __syncthreads();
    {   // barrier 0: init complete
        unsigned tgt = base + 1;
        if (tid == 0) st_rel(&g_flags[cta], tgt);
        if (tid < NCTA)
            while ((int)(ld_acq(&g_flags[tid]) - tgt) < 0) {}
        __syncthreads();
    }

    const int eb = tid >> 2, ej = tid & 3;    // cell-update mapping
    const int colj = (cta << 2) + ej;
    float c_reg = 0.f;

    for (int t = 0; t < T_; t++) {
        const float* hsrc = g_hbuf[t & 1];

        // group 0: chunk 0 + x_proj slice; group 1: chunk 1
        {
#pragma unroll
            for (int j = 0; j < 8; j++) {
                int i = tid + j * 256;
                int row = i >> 4, seg = i & 15;
                cp16(sh + row * SH_STRIDE + seg * 4, hsrc + row * 64 + seg * 4);
            }
            int b = tid >> 2, g = tid & 3;
            cp16(sx + b * 16 + g * 4,
                 g_xproj + ((size_t)(t * 64 + b) << 11) + ((size_t)g << 9) + (cta << 2));
            asm volatile("cp.async.commit_group;" ::: "memory");
#pragma unroll
            for (int j = 0; j < 8; j++) {
                int i = tid + j * 256;
                int row = i >> 4, seg = i & 15;
                cp16(sh + SH_CHUNK + row * SH_STRIDE + seg * 4,
                     hsrc + 8192 + row * 64 + seg * 4);
            }
            asm volatile("cp.async.commit_group;" ::: "memory");
        }

        float acc[4][2][4];
#pragma unroll
        for (int mt = 0; mt < 4; mt++)
#pragma unroll
            for (int nt = 0; nt < 2; nt++)
#pragma unroll
                for (int k = 0; k < 4; k++) acc[mt][nt][k] = 0.f;

        for (int ch = 0; ch < 4; ch++) {
            if (ch < 3) { asm volatile("cp.async.wait_group 1;" ::: "memory"); }
            else        { asm volatile("cp.async.wait_group 0;" ::: "memory"); }
            __syncthreads();

            if (ch < 2) {   // issue chunk ch+2 into ring buffer (ch+2)%3
                const float* src = hsrc + (ch + 2) * 8192;
                float* dst = sh + ((ch + 2) % 3) * SH_CHUNK;
#pragma unroll
                for (int j = 0; j < 8; j++) {
                    int i = tid + j * 256;
                    int row = i >> 4, seg = i & 15;
                    cp16(dst + row * SH_STRIDE + seg * 4, src + row * 64 + seg * 4);
                }
                asm volatile("cp.async.commit_group;" ::: "memory");
            }

            const float* hb = sh + (ch % 3) * SH_CHUNK;
#pragma unroll
            for (int j = 0; j < 2; j++) {
                const int lk0 = ((j << 3) + warp) << 3;   // local k-row in [0,128)
                unsigned a[4][4];
#pragma unroll
                for (int mt = 0; mt < 4; mt++) {
                    const float* ap = hb + (lk0 + cq) * SH_STRIDE + mt * 16 + r;
                    a[mt][0] = __float_as_uint(ap[0]);
                    a[mt][1] = __float_as_uint(ap[8]);
                    a[mt][2] = __float_as_uint(ap[4 * SH_STRIDE]);
                    a[mt][3] = __float_as_uint(ap[4 * SH_STRIDE + 8]);
                }
                const int bi0 = (ch << 2) | (j << 1);
#pragma unroll
                for (int nt = 0; nt < 2; nt++)
#pragma unroll
                    for (int mt = 0; mt < 4; mt++)
                        mma8(acc[mt][nt], a[mt][0], a[mt][1], a[mt][2], a[mt][3],
                             BH[bi0 | nt][0], BH[bi0 | nt][1]);
#pragma unroll
                for (int nt = 0; nt < 2; nt++)
#pragma unroll
                    for (int mt = 0; mt < 4; mt++)
                        mma8(acc[mt][nt], a[mt][0], a[mt][1], a[mt][2], a[mt][3],
                             BL[bi0 | nt][0], BL[bi0 | nt][1]);
            }
        }

        // split-k partials -> smem
        {
            float* sgp = sg + warp * SG_WARP;
#pragma unroll
            for (int mt = 0; mt < 4; mt++) {
                int b0 = mt * 16 + r;
#pragma unroll
                for (int nt = 0; nt < 2; nt++) {
                    int n = nt * 8 + cq * 2;
                    *(float2*)&sgp[b0 * SG_STRIDE + n] =
                        make_float2(acc[mt][nt][0], acc[mt][nt][1]);
                    *(float2*)&sgp[(b0 + 8) * SG_STRIDE + n] =
                        make_float2(acc[mt][nt][2], acc[mt][nt][3]);
                }
            }
        }
        __syncthreads();

        // cell update: thread -> (eb, ej); gates i,f,g,o at n = g*4 + ej
        {
            float v[4];
#pragma unroll
            for (int g = 0; g < 4; g++) {
                int n = (g << 2) + ej;
                float s = sx[eb * 16 + n];
#pragma unroll
                for (int w = 0; w < 8; w++) s += sg[w * SG_WARP + eb * SG_STRIDE + n];
                v[g] = s;
            }
            float si = 1.f / (1.f + __expf(-v[0]));
            float sf = 1.f / (1.f + __expf(-v[1]));
            float tg = tanhf(v[2]);
            float so = 1.f / (1.f + __expf(-v[3]));
            c_reg = sf * c_reg + si * tg;
            float hn = so * tanhf(c_reg);

            g_hbuf[(t + 1) & 1][(colj << 6) + eb] = hn;

            if (t == T_ - 1) {
                out[eb * H_ + colj]           = c_reg;   // c_fin
                out[B_ * H_ + eb * H_ + colj] = hn;      // h_fin
            }
        }

        // grid barrier for step t: syncthreads (CTA h-writes happen-before),
        // release own flag, pure-spin acquire-poll all flags, resync.
        __syncthreads();
        {
            unsigned tgt = base + 2 + (unsigned)t;
            if (tid == 0) st_rel(&g_flags[cta], tgt);
            if (tid < NCTA)
                while ((int)(ld_acq(&g_flags[tid]) - tgt) < 0) {}
            __syncthreads();
        }
    }
}

// ---------------------------------------------------------------------------
extern "C" void kernel_launch(void* const* d_in, const int* in_sizes, int n_in,
                              void* d_out, int out_size)
{
    const float* inputs = (const float*)d_in[0];  // [B, T, F]
    const float* Wx     = (const float*)d_in[1];  // [F, 4H]
    const float* Wh     = (const float*)d_in[2];  // [H, 4H]
    const float* bias   = (const float*)d_in[3];  // [4H]
    float* out = (float*)d_out;                   // [2, B, H] = (c_fin, h_fin)

    (void)in_sizes; (void)n_in; (void)out_size;

    const int gemm_smem = (2 * AS_SZ + 2 * BS_SZ) * (int)sizeof(float);
    cudaFuncSetAttribute(gemm_xproj, cudaFuncAttributeMaxDynamicSharedMemorySize, gemm_smem);
    gemm_xproj<<<dim3(G4_ / 128, (B_ * T_) / 128), 256, gemm_smem>>>(inputs, Wx, bias);

    const int lstm_smem = (3 * SH_CHUNK + 8 * SG_WARP + 64 * 16) * (int)sizeof(float); // 151552 B
    cudaFuncSetAttribute(lstm_kernel, cudaFuncAttributeMaxDynamicSharedMemorySize, lstm_smem);
    lstm_kernel<<<NCTA, 256, lstm_smem>>>(Wh, out);
}

// round 5
// speedup vs baseline: 3.3601x; 1.8100x over previous
#include <cuda_runtime.h>
#include <cstdint>
#include <cstddef>

#define B_  64
#define T_  1024
#define F_  512
#define H_  512
#define G4_ 2048   // 4H
#define NCTA 128

__device__ float g_xproj[(size_t)T_ * B_ * G4_];   // [t][b][col]
__device__ float g_hbuf[2][H_ * B_];               // [col(k)][b] transposed, double-buffered
__device__ unsigned g_flags[NCTA * 32];            // padded: 1 flag per 128B line

// ---------------------------------------------------------------------------
__device__ __forceinline__ void cp16(float* dst, const float* src)
{
    unsigned d = (unsigned)__cvta_generic_to_shared(dst);
    asm volatile("cp.async.cg.shared.global [%0], [%1], 16;" :: "r"(d), "l"(src) : "memory");
}

__device__ __forceinline__ unsigned ld_acq(const unsigned* p)
{
    unsigned v;
    asm volatile("ld.acquire.gpu.global.u32 %0, [%1];" : "=r"(v) : "l"(p) : "memory");
    return v;
}

__device__ __forceinline__ void st_rel(unsigned* p, unsigned v)
{
    asm volatile("st.release.gpu.global.u32 [%0], %1;" :: "l"(p), "r"(v) : "memory");
}

// lo part of the tf32 split: x - truncate_to_tf32(x)  (exact in fp32)
__device__ __forceinline__ float tf32_lo(float x)
{
    unsigned u = __float_as_uint(x) & 0xFFFFE000u;
    return x - __uint_as_float(u);
}

__device__ __forceinline__ void mma8(float* c,
    unsigned a0, unsigned a1, unsigned a2, unsigned a3,
    unsigned b0, unsigned b1)
{
    asm volatile(
        "mma.sync.aligned.m16n8k8.row.col.f32.tf32.tf32.f32 "
        "{%0,%1,%2,%3}, {%4,%5,%6,%7}, {%8,%9}, {%0,%1,%2,%3};"
        : "+f"(c[0]), "+f"(c[1]), "+f"(c[2]), "+f"(c[3])
        : "r"(a0), "r"(a1), "r"(a2), "r"(a3), "r"(b0), "r"(b1));
}

// ---------------------------------------------------------------------------
// Kernel 1: x_proj = inputs @ Wx + bias  (2-term tf32)  [UNCHANGED from R4]
// ---------------------------------------------------------------------------
#define AS_STRIDE 36
#define BS_STRIDE 136
#define AS_SZ (128 * AS_STRIDE)
#define BS_SZ (32 * BS_STRIDE)

__global__ void __launch_bounds__(256, 1) gemm_xproj(
    const float* __restrict__ A,
    const float* __restrict__ W,
    const float* __restrict__ bias)
{
    extern __shared__ float gs[];
    float* As = gs;
    float* Bs = gs + 2 * AS_SZ;

    const int tid = threadIdx.x;
    const int n0  = blockIdx.x * 128;
    const int m0  = blockIdx.y * 128;
    const int warp = tid >> 5, lane = tid & 31;
    const int wm = warp & 1, wn = warp >> 1;
    const int r  = lane >> 2, cq = lane & 3;

    float acc[4][4][4];
#pragma unroll
    for (int i = 0; i < 4; i++)
#pragma unroll
        for (int j = 0; j < 4; j++)
#pragma unroll
            for (int k = 0; k < 4; k++) acc[i][j][k] = 0.f;

    auto issue = [&](int s, int bi) {
        const float* Ag = A + (size_t)m0 * 512 + s * 32;
        float* Ad = As + bi * AS_SZ;
#pragma unroll
        for (int j = 0; j < 4; j++) {
            int q = tid + j * 256;
            int row = q >> 3, seg = q & 7;
            cp16(Ad + row * AS_STRIDE + seg * 4, Ag + (size_t)row * 512 + seg * 4);
        }
        const float* Bg = W + (size_t)(s * 32) * G4_ + n0;
        float* Bd = Bs + bi * BS_SZ;
#pragma unroll
        for (int j = 0; j < 4; j++) {
            int q = tid + j * 256;
            int row = q >> 5, seg = q & 31;
            cp16(Bd + row * BS_STRIDE + seg * 4, Bg + (size_t)row * G4_ + seg * 4);
        }
        asm volatile("cp.async.commit_group;" ::: "memory");
    };

    issue(0, 0);

    for (int s = 0; s < 16; s++) {
        if (s < 15) {
            issue(s + 1, (s + 1) & 1);
            asm volatile("cp.async.wait_group 1;" ::: "memory");
        } else {
            asm volatile("cp.async.wait_group 0;" ::: "memory");
        }
        __syncthreads();

        const float* Ab = As + (s & 1) * AS_SZ + (wm * 64) * AS_STRIDE;
        const float* Bb = Bs + (s & 1) * BS_SZ + wn * 32;

#pragma unroll
        for (int k8 = 0; k8 < 4; k8++) {
            unsigned aH[4][4];
#pragma unroll
            for (int mt = 0; mt < 4; mt++) {
                const float* ap = Ab + (mt * 16 + r) * AS_STRIDE + k8 * 8 + cq;
                aH[mt][0] = __float_as_uint(ap[0]);
                aH[mt][1] = __float_as_uint(ap[8 * AS_STRIDE]);
                aH[mt][2] = __float_as_uint(ap[4]);
                aH[mt][3] = __float_as_uint(ap[8 * AS_STRIDE + 4]);
            }
            unsigned bH[4][2], bL[4][2];
#pragma unroll
            for (int nt = 0; nt < 4; nt++) {
                const float* bp = Bb + (k8 * 8 + cq) * BS_STRIDE + nt * 8 + r;
                float y0 = bp[0];
                float y1 = bp[4 * BS_STRIDE];
                bH[nt][0] = __float_as_uint(y0);
                bH[nt][1] = __float_as_uint(y1);
                bL[nt][0] = __float_as_uint(tf32_lo(y0));
                bL[nt][1] = __float_as_uint(tf32_lo(y1));
            }
#pragma unroll
            for (int nt = 0; nt < 4; nt++)
#pragma unroll
                for (int mt = 0; mt < 4; mt++)
                    mma8(acc[mt][nt], aH[mt][0], aH[mt][1], aH[mt][2], aH[mt][3], bH[nt][0], bH[nt][1]);
#pragma unroll
            for (int nt = 0; nt < 4; nt++)
#pragma unroll
                for (int mt = 0; mt < 4; mt++)
                    mma8(acc[mt][nt], aH[mt][0], aH[mt][1], aH[mt][2], aH[mt][3], bL[nt][0], bL[nt][1]);
        }
        __syncthreads();
    }

    const int mbase = m0 + wm * 64;
    const int nbase = n0 + wn * 32;
#pragma unroll
    for (int nt = 0; nt < 4; nt++) {
        int nn = nbase + nt * 8 + cq * 2;
        float2 bb = *(const float2*)(bias + nn);
#pragma unroll
        for (int mt = 0; mt < 4; mt++) {
            int row0 = mbase + mt * 16 + r;
            int t0 = row0 & (T_ - 1), bi0 = row0 >> 10;
            float2 v0 = make_float2(acc[mt][nt][0] + bb.x, acc[mt][nt][1] + bb.y);
            *(float2*)&g_xproj[((size_t)(t0 * 64 + bi0) << 11) + nn] = v0;
            int row1 = row0 + 8;
            int t1 = row1 & (T_ - 1), bi1 = row1 >> 10;
            float2 v1 = make_float2(acc[mt][nt][2] + bb.x, acc[mt][nt][3] + bb.y);
            *(float2*)&g_xproj[((size_t)(t1 * 64 + bi1) << 11) + nn] = v1;
        }
    }
}

// ---------------------------------------------------------------------------
// Kernel 2: persistent LSTM recurrence — warp-local h pipeline.
// Warp w consumes ONLY k-rows {(8j+w)*8..+8} of each 128-row chunk, and now
// also LOADS exactly those rows itself -> no block syncs in the chunk loop
// (cp.async.wait_group per-lane + __syncwarp suffices; ring hazards warp-local).
// x_proj prefetched one step ahead (double-buffered sx), committed with c2.
// Flags padded to 128B lines. 2 block syncs + 1 grid barrier per step.
// ---------------------------------------------------------------------------
#define SH_STRIDE 72
#define SH_CHUNK (128 * SH_STRIDE)
#define SG_STRIDE 18
#define SG_WARP  (64 * SG_STRIDE)

__global__ void __launch_bounds__(256, 1) lstm_kernel(
    const float* __restrict__ Wh,
    float* __restrict__ out)
{
    extern __shared__ float smem[];
    float* sh = smem;                    // 3 * 128*72 = 27648 floats
    float* sg = sh + 3 * SH_CHUNK;       // 8 * 64*18  =  9216 floats
    float* sx = sg + 8 * SG_WARP;        // 2 * 64*16  =  2048 floats

    const int tid = threadIdx.x;
    const int cta = blockIdx.x;
    const int warp = tid >> 5, lane = tid & 31;
    const int r = lane >> 2, cq = lane & 3;

    const unsigned base = ld_acq(&g_flags[cta * 32]);

    // Preload Wh fragments (hi + lo) into registers: 8 ktiles x 2 nt x 2 regs.
    unsigned BH[16][2], BL[16][2];
#pragma unroll
    for (int c = 0; c < 4; c++)
#pragma unroll
        for (int j = 0; j < 2; j++) {
            int kt = c * 16 + j * 8 + warp;
            int k0 = kt << 3;
#pragma unroll
            for (int nt = 0; nt < 2; nt++) {
                int n = nt * 8 + r;
                int col = ((n >> 2) << 9) + (cta << 2) + (n & 3);
                float w0 = Wh[(size_t)(k0 + cq) * G4_ + col];
                float w1 = Wh[(size_t)(k0 + cq + 4) * G4_ + col];
                int bi = (c << 2) | (j << 1) | nt;
                BH[bi][0] = __float_as_uint(w0);
                BH[bi][1] = __float_as_uint(w1);
                BL[bi][0] = __float_as_uint(tf32_lo(w0));
                BL[bi][1] = __float_as_uint(tf32_lo(w1));
            }
        }

    g_hbuf[0][(cta << 8) + tid] = 0.f;

    // prefetch x_proj(t=0) into sx[0]
    {
        int b = tid >> 2, g = tid & 3;
        cp16(sx + b * 16 + g * 4,
             g_xproj + ((size_t)b << 11) + ((size_t)g << 9) + (cta << 2));
        asm volatile("cp.async.commit_group;" ::: "memory");
        asm volatile("cp.async.wait_group 0;" ::: "memory");
    }

    __syncthreads();
    {   // barrier 0: init complete
        unsigned tgt = base + 1;
        if (tid == 0) st_rel(&g_flags[cta * 32], tgt);
        if (tid < NCTA)
            while ((int)(ld_acq(&g_flags[tid * 32]) - tgt) < 0) {}
        __syncthreads();
    }

    const int eb = tid >> 2, ej = tid & 3;    // cell-update mapping
    const int colj = (cta << 2) + ej;
    float c_reg = 0.f;

    // warp-local chunk copy: warp loads exactly its own 16 rows (2x8) per chunk.
    auto issue_chunk = [&](const float* hsrc, int ch) {
        const int buf = ch % 3;
#pragma unroll
        for (int j = 0; j < 2; j++) {
            const float* s0 = hsrc + (size_t)(ch * 128 + j * 64 + warp * 8) * 64;
            float* d0 = sh + buf * SH_CHUNK + (j * 64 + warp * 8) * SH_STRIDE;
#pragma unroll
            for (int i = 0; i < 4; i++) {
                int s_ = lane + 32 * i;        // 0..127 (16B units over 2KB)
                int row8 = s_ >> 4, segc = s_ & 15;
                cp16(d0 + row8 * SH_STRIDE + segc * 4, s0 + row8 * 64 + segc * 4);
            }
        }
    };

    for (int t = 0; t < T_; t++) {
        const float* hsrc = g_hbuf[t & 1];

        issue_chunk(hsrc, 0);
        asm volatile("cp.async.commit_group;" ::: "memory");
        issue_chunk(hsrc, 1);
        asm volatile("cp.async.commit_group;" ::: "memory");

        float acc[4][2][4];
#pragma unroll
        for (int mt = 0; mt < 4; mt++)
#pragma unroll
            for (int nt = 0; nt < 2; nt++)
#pragma unroll
                for (int k = 0; k < 4; k++) acc[mt][nt][k] = 0.f;

#pragma unroll
        for (int ch = 0; ch < 4; ch++) {
            if (ch < 3) { asm volatile("cp.async.wait_group 1;" ::: "memory"); }
            else        { asm volatile("cp.async.wait_group 0;" ::: "memory"); }
            __syncwarp();

            // prefetch: ch0 -> {c2, xproj(t+1)}; ch1 -> {c3}
            if (ch == 0) {
                issue_chunk(hsrc, 2);
                if (t + 1 < T_) {
                    int b = tid >> 2, g = tid & 3;
                    cp16(sx + ((t + 1) & 1) * 1024 + b * 16 + g * 4,
                         g_xproj + ((size_t)((t + 1) * 64 + b) << 11)
                                 + ((size_t)g << 9) + (cta << 2));
                }
                asm volatile("cp.async.commit_group;" ::: "memory");
            } else if (ch == 1) {
                issue_chunk(hsrc, 3);
                asm volatile("cp.async.commit_group;" ::: "memory");
            }

            const float* hb = sh + (ch % 3) * SH_CHUNK;
#pragma unroll
            for (int j = 0; j < 2; j++) {
                const int lk0 = ((j << 3) + warp) << 3;   // local k-row in [0,128)
                unsigned a[4][4];
#pragma unroll
                for (int mt = 0; mt < 4; mt++) {
                    const float* ap = hb + (lk0 + cq) * SH_STRIDE + mt * 16 + r;
                    a[mt][0] = __float_as_uint(ap[0]);
                    a[mt][1] = __float_as_uint(ap[8]);
                    a[mt][2] = __float_as_uint(ap[4 * SH_STRIDE]);
                    a[mt][3] = __float_as_uint(ap[4 * SH_STRIDE + 8]);
                }
                const int bi0 = (ch << 2) | (j << 1);
#pragma unroll
                for (int nt = 0; nt < 2; nt++)
#pragma unroll
                    for (int mt = 0; mt < 4; mt++)
                        mma8(acc[mt][nt], a[mt][0], a[mt][1], a[mt][2], a[mt][3],
                             BH[bi0 | nt][0], BH[bi0 | nt][1]);
#pragma unroll
                for (int nt = 0; nt < 2; nt++)
#pragma unroll
                    for (int mt = 0; mt < 4; mt++)
                        mma8(acc[mt][nt], a[mt][0], a[mt][1], a[mt][2], a[mt][3],
                             BL[bi0 | nt][0], BL[bi0 | nt][1]);
            }
        }

        // split-k partials -> smem
        {
            float* sgp = sg + warp * SG_WARP;
#pragma unroll
            for (int mt = 0; mt < 4; mt++) {
                int b0 = mt * 16 + r;
#pragma unroll
                for (int nt = 0; nt < 2; nt++) {
                    int n = nt * 8 + cq * 2;
                    *(float2*)&sgp[b0 * SG_STRIDE + n] =
                        make_float2(acc[mt][nt][0], acc[mt][nt][1]);
                    *(float2*)&sgp[(b0 + 8) * SG_STRIDE + n] =
                        make_float2(acc[mt][nt][2], acc[mt][nt][3]);
                }
            }
        }
        __syncthreads();

        // cell update: thread -> (eb, ej); gates i,f,g,o at n = g*4 + ej
        {
            const float* sxb = sx + (t & 1) * 1024;
            float v[4];
#pragma unroll
            for (int g = 0; g < 4; g++) {
                int n = (g << 2) + ej;
                float s = sxb[eb * 16 + n];
#pragma unroll
                for (int w = 0; w < 8; w++) s += sg[w * SG_WARP + eb * SG_STRIDE + n];
                v[g] = s;
            }
            float si = 1.f / (1.f + __expf(-v[0]));
            float sf = 1.f / (1.f + __expf(-v[1]));
            float tg = tanhf(v[2]);
            float so = 1.f / (1.f + __expf(-v[3]));
            c_reg = sf * c_reg + si * tg;
            float hn = so * tanhf(c_reg);

            g_hbuf[(t + 1) & 1][(colj << 6) + eb] = hn;

            if (t == T_ - 1) {
                out[eb * H_ + colj]           = c_reg;   // c_fin
                out[B_ * H_ + eb * H_ + colj] = hn;      // h_fin
            }
        }

        __syncthreads();
        {   // grid barrier for step t
            unsigned tgt = base + 2 + (unsigned)t;
            if (tid == 0) st_rel(&g_flags[cta * 32], tgt);
            if (tid < NCTA)
                while ((int)(ld_acq(&g_flags[tid * 32]) - tgt) < 0) {}
            __syncthreads();
        }
    }
}

// ---------------------------------------------------------------------------
extern "C" void kernel_launch(void* const* d_in, const int* in_sizes, int n_in,
                              void* d_out, int out_size)
{
    const float* inputs = (const float*)d_in[0];  // [B, T, F]
    const float* Wx     = (const float*)d_in[1];  // [F, 4H]
    const float* Wh     = (const float*)d_in[2];  // [H, 4H]
    const float* bias   = (const float*)d_in[3];  // [4H]
    float* out = (float*)d_out;                   // [2, B, H] = (c_fin, h_fin)

    (void)in_sizes; (void)n_in; (void)out_size;

    const int gemm_smem = (2 * AS_SZ + 2 * BS_SZ) * (int)sizeof(float);
    cudaFuncSetAttribute(gemm_xproj, cudaFuncAttributeMaxDynamicSharedMemorySize, gemm_smem);
    gemm_xproj<<<dim3(G4_ / 128, (B_ * T_) / 128), 256, gemm_smem>>>(inputs, Wx, bias);

    const int lstm_smem = (3 * SH_CHUNK + 8 * SG_WARP + 2 * 1024) * (int)sizeof(float); // 155648 B
    cudaFuncSetAttribute(lstm_kernel, cudaFuncAttributeMaxDynamicSharedMemorySize, lstm_smem);
    lstm_kernel<<<NCTA, 256, lstm_smem>>>(Wh, out);
}